// round 10
// baseline (speedup 1.0000x reference)
#include <cuda_runtime.h>
#include <cuda_bf16.h>

// out[n,:] = trace-contraction of the Jacobian of the antisymmetric field
// A(p)=M-M^T (M upper-tri from v=MLP(p), 3->32->32->32->3, softplus beta=20):
//   out0 =  Jv[0][1] + Jv[1][2]
//   out1 = -Jv[0][0] + Jv[2][2]
//   out2 = -Jv[1][0] - Jv[2][1],   Jv[c][j] = dv_c/dx_j
// Forward (sigmoid(20z) diagonals) + 3 simultaneous forward-mode tangents.
//
// R9 decomposition (raise occupancy; R8 was latency-bound at 8 warps/SM,
// regs=222): warp = ONE sample, lane = ONE column. Weight registers halve
// (64 regs: 16 k-pair f32x2 ulls per matrix), arch regs ~130 ->
// launch_bounds(128,3) = 12 warps/SM. Exchange reads are full-warp broadcast
// LDS.128; f32x2 packs the K axis; x is prefetched one iteration ahead.

#define BETAF 20.0f
#define INV_BETAF 0.05f
#define BLOCK 128
#define WPB (BLOCK / 32)
#define GRID 456   // 152 SMs x 3 resident blocks, persistent loop

typedef unsigned long long ull;

__device__ __forceinline__ ull pk2(float lo, float hi) {
    ull d;
    asm("mov.b64 %0, {%1, %2};" : "=l"(d)
        : "r"(__float_as_uint(lo)), "r"(__float_as_uint(hi)));
    return d;
}
__device__ __forceinline__ float hadd2(ull s) {
    unsigned l, h;
    asm("mov.b64 {%0, %1}, %2;" : "=r"(l), "=r"(h) : "l"(s));
    return __uint_as_float(l) + __uint_as_float(h);
}
#define FMA2(d,a,b,c) asm("fma.rn.f32x2 %0, %1, %2, %3;" : "=l"(d) : "l"(a), "l"(b), "l"(c))
#define ADD2(d,a,b)   asm("add.rn.f32x2 %0, %1, %2;"     : "=l"(d) : "l"(a), "l"(b))

__device__ __forceinline__ void act_hd(float z, float& h, float& d) {
    float y = BETAF * z;
    float e = __expf(-fabsf(y));
    float r = __fdividef(1.0f, 1.0f + e);
    d = (y >= 0.0f) ? r : e * r;                       // sigmoid(20z)
    h = fmaxf(z, 0.0f) + __logf(1.0f + e) * INV_BETAF; // softplus(20z)/20
}
__device__ __forceinline__ float act_d(float z) {
    float y = BETAF * z;
    float e = __expf(-fabsf(y));
    float r = __fdividef(1.0f, 1.0f + e);
    return (y >= 0.0f) ? r : e * r;
}

// weight k-pair register: P##i = (G[2i][lane], G[2i+1][lane])
#define LWK(i, P, G) const ull P##i = pk2((G)[(2*(i))*32 + lane], (G)[(2*(i)+1)*32 + lane]);
#define REP16(F, P, G) F(0,P,G)F(1,P,G)F(2,P,G)F(3,P,G)F(4,P,G)F(5,P,G)F(6,P,G)F(7,P,G) \
    F(8,P,G)F(9,P,G)F(10,P,G)F(11,P,G)F(12,P,G)F(13,P,G)F(14,P,G)F(15,P,G)

// forward chunk i: one broadcast LDS.128 = k-values 4i..4i+3 ; 2 FMA2
#define FWDC(P, i, j0, j1, B) { \
    const ulonglong2 v = reinterpret_cast<const ulonglong2*>(B)[i]; \
    FMA2(accA, v.x, P##j0, accA); FMA2(accB, v.y, P##j1, accB); }
#define FWD_ALL(P, B) \
    FWDC(P,0,0,1,B) FWDC(P,1,2,3,B) FWDC(P,2,4,5,B) FWDC(P,3,6,7,B) \
    FWDC(P,4,8,9,B) FWDC(P,5,10,11,B) FWDC(P,6,12,13,B) FWDC(P,7,14,15,B)

// tangent chunk i: 3 broadcast LDS.128 (one per tangent), 6 FMA2
#define TRIC(P, i, j0, j1, T) { \
    const ulonglong2 v0 = reinterpret_cast<const ulonglong2*>(T)[i]; \
    const ulonglong2 v1 = reinterpret_cast<const ulonglong2*>((T)+32)[i]; \
    const ulonglong2 v2 = reinterpret_cast<const ulonglong2*>((T)+64)[i]; \
    FMA2(t0, v0.x, P##j0, t0); FMA2(t0, v0.y, P##j1, t0); \
    FMA2(t1, v1.x, P##j0, t1); FMA2(t1, v1.y, P##j1, t1); \
    FMA2(t2, v2.x, P##j0, t2); FMA2(t2, v2.y, P##j1, t2); }
#define TRI_ALL(P, T) \
    TRIC(P,0,0,1,T) TRIC(P,1,2,3,T) TRIC(P,2,4,5,T) TRIC(P,3,6,7,T) \
    TRIC(P,4,8,9,T) TRIC(P,5,10,11,T) TRIC(P,6,12,13,T) TRIC(P,7,14,15,T)

// per-warp exchange buffer (floats): hb1[32] hb2[32] tb1[96] tb2[96] = 256
#define WARP_FLOATS 256

__global__ __launch_bounds__(BLOCK, 3) void NCL_50766513438744_kernel(
    const float* __restrict__ x,
    const float* __restrict__ W1, const float* __restrict__ b1,
    const float* __restrict__ W2, const float* __restrict__ b2,
    const float* __restrict__ W3, const float* __restrict__ b3,
    const float* __restrict__ W4,
    float* __restrict__ out, int N, int totalWarps)
{
    __shared__ __align__(16) float sBuf[WPB * WARP_FLOATS];

    const int lane = threadIdx.x & 31;
    const int wib  = threadIdx.x >> 5;

    float* const hb1 = &sBuf[wib * WARP_FLOATS];
    float* const hb2 = hb1 + 32;
    float* const tb1 = hb1 + 64;
    float* const tb2 = hb1 + 160;

    // loop-invariant weights: column `lane`, k-pair packed
    REP16(LWK, w2, W2)
    REP16(LWK, w3, W3)
    const float w1_0 = W1[lane], w1_1 = W1[32 + lane], w1_2 = W1[64 + lane];
    const float b1m = b1[lane], b2m = b2[lane], b3m = b3[lane];
    const float w40 = W4[lane * 3 + 0], w41 = W4[lane * 3 + 1], w42 = W4[lane * 3 + 2];

    const int gw = blockIdx.x * WPB + wib;
    if (gw >= N) return;

    // prefetch first sample's x (uniform across warp)
    float x0 = __ldg(x + 3 * gw + 0);
    float x1 = __ldg(x + 3 * gw + 1);
    float x2 = __ldg(x + 3 * gw + 2);

    for (int s = gw; s < N; s += totalWarps) {
        // ===== phase A: layer 1 + tangent seeds (column `lane`) =====
        float h1v, d1v;
        act_hd(fmaf(x0, w1_0, fmaf(x1, w1_1, fmaf(x2, w1_2, b1m))), h1v, d1v);
        hb1[lane]      = h1v;
        tb1[lane]      = d1v * w1_0;
        tb1[32 + lane] = d1v * w1_1;
        tb1[64 + lane] = d1v * w1_2;
        __syncwarp();

        // prefetch next iteration's x (hides DRAM latency under phases B/C)
        {
            const int sn = s + totalWarps;
            const int sc = (sn < N) ? sn : s;
            x0 = __ldg(x + 3 * sc + 0);
            x1 = __ldg(x + 3 * sc + 1);
            x2 = __ldg(x + 3 * sc + 2);
        }

        // ===== phase B: layer-2 forward + tangent layer 2 =====
        ull accA = pk2(b2m, 0.0f), accB = 0ull;
        FWD_ALL(w2, hb1)
        ull t0 = 0ull, t1 = 0ull, t2 = 0ull;
        TRI_ALL(w2, tb1)
        ADD2(accA, accA, accB);
        float h2v, d2v;
        act_hd(hadd2(accA), h2v, d2v);
        hb2[lane]      = h2v;
        tb2[lane]      = d2v * hadd2(t0);
        tb2[32 + lane] = d2v * hadd2(t1);
        tb2[64 + lane] = d2v * hadd2(t2);
        __syncwarp();

        // ===== phase C: layer-3 forward (deriv only) + tangent layer 3 =====
        accA = pk2(b3m, 0.0f); accB = 0ull;
        FWD_ALL(w3, hb2)
        t0 = 0ull; t1 = 0ull; t2 = 0ull;
        TRI_ALL(w3, tb2)
        ADD2(accA, accA, accB);
        const float d3v = act_d(hadd2(accA));
        const float s0 = d3v * hadd2(t0);
        const float s1 = d3v * hadd2(t1);
        const float s2 = d3v * hadd2(t2);

        // layer 4 + antisymmetric trace contraction (this lane's column)
        float po0 = fmaf(s1, w40, s2 * w41);
        float po1 = fmaf(s2, w42, -(s0 * w40));
        float po2 = -fmaf(s0, w41, s1 * w42);

        #pragma unroll
        for (int off = 16; off; off >>= 1) {
            po0 += __shfl_xor_sync(0xffffffffu, po0, off);
            po1 += __shfl_xor_sync(0xffffffffu, po1, off);
            po2 += __shfl_xor_sync(0xffffffffu, po2, off);
        }
        if (lane == 0) {
            out[3 * s + 0] = po0;
            out[3 * s + 1] = po1;
            out[3 * s + 2] = po2;
        }
        // ordering: next-A writes (hb1/tb1) vs this-B reads -> end-of-B syncwarp;
        // this-C reads (hb2/tb2) vs next-B writes -> end-of-A syncwarp. Safe.
    }
}

extern "C" void kernel_launch(void* const* d_in, const int* in_sizes, int n_in,
                              void* d_out, int out_size) {
    const float* x  = (const float*)d_in[0];
    const float* W1 = (const float*)d_in[1];
    const float* b1 = (const float*)d_in[2];
    const float* W2 = (const float*)d_in[3];
    const float* b2 = (const float*)d_in[4];
    const float* W3 = (const float*)d_in[5];
    const float* b3 = (const float*)d_in[6];
    const float* W4 = (const float*)d_in[7];
    // d_in[8] = b4: not needed (bias drops out of the Jacobian)
    float* out = (float*)d_out;

    const int N = in_sizes[0] / 3;
    const int totalWarps = GRID * WPB;
    NCL_50766513438744_kernel<<<GRID, BLOCK>>>(x, W1, b1, W2, b2, W3, b3, W4,
                                               out, N, totalWarps);
}

// round 11
// speedup vs baseline: 1.3488x; 1.3488x over previous
#include <cuda_runtime.h>
#include <cuda_bf16.h>

// out[n,:] = trace-contraction of the Jacobian of the antisymmetric field
// A(p)=M-M^T (M upper-tri from v=MLP(p), 3->32->32->32->3, softplus beta=20):
//   out0 =  Jv[0][1] + Jv[1][2]
//   out1 = -Jv[0][0] + Jv[2][2]
//   out2 = -Jv[1][0] - Jv[2][1],   Jv[c][j] = dv_c/dx_j
// Forward (sigmoid(20z) diagonals) + 3 simultaneous forward-mode tangents.
//
// R10: QUARTER-warp per sample (4 samples/warp), lane owns 4 columns.
//  - exchange LDS.128 broadcast serves 4 samples (buffers strided 16B mod 128
//    -> 4 lines, 1 wavefront): 16 exchange-LDS per sample.
//  - weights in smem, blocked [kpair][colpair-E/O] so 8 lanes read 128B
//    contiguous, quarters broadcast: 16 weight-LDS per sample, ~0 weight regs.
//  - regs ~100 -> launch_bounds(128,4) = 16 warps/SM (2x R8's occupancy).
// f32x2 packs the K axis (FMA2 against (W[2i],W[2i+1]) pairs, hadd at end).

#define BETAF 20.0f
#define INV_BETAF 0.05f
#define BLOCK 128
#define WPB (BLOCK / 32)
#define GRID 608   // 152 SMs x 4 resident blocks, persistent loop

typedef unsigned long long ull;

__device__ __forceinline__ ull pk2(float lo, float hi) {
    ull d;
    asm("mov.b64 %0, {%1, %2};" : "=l"(d)
        : "r"(__float_as_uint(lo)), "r"(__float_as_uint(hi)));
    return d;
}
__device__ __forceinline__ float hadd2(ull s) {
    unsigned l, h;
    asm("mov.b64 {%0, %1}, %2;" : "=r"(l), "=r"(h) : "l"(s));
    return __uint_as_float(l) + __uint_as_float(h);
}
#define FMA2(d,a,b,c) asm("fma.rn.f32x2 %0, %1, %2, %3;" : "=l"(d) : "l"(a), "l"(b), "l"(c))

__device__ __forceinline__ void act_hd(float z, float& h, float& d) {
    float y = BETAF * z;
    float e = __expf(-fabsf(y));
    float r = __fdividef(1.0f, 1.0f + e);
    d = (y >= 0.0f) ? r : e * r;                       // sigmoid(20z)
    h = fmaxf(z, 0.0f) + __logf(1.0f + e) * INV_BETAF; // softplus(20z)/20
}
__device__ __forceinline__ float act_d(float z) {
    float y = BETAF * z;
    float e = __expf(-fabsf(y));
    float r = __fdividef(1.0f, 1.0f + e);
    return (y >= 0.0f) ? r : e * r;
}

// fused fwd + 3-tangent chunk c (k-values 4c..4c+3) for one 32x32 layer.
// WE/WO: blocked weight arrays; HB/TB: this sample's h / t buffers (floats).
#define CHUNK(WE, WO, HB, TB, c) { \
    const ulonglong2 hv = ((const ulonglong2*)(HB))[c]; \
    const ulonglong2 wA = (WE)[(2*(c)    )*8 + q]; \
    const ulonglong2 wB = (WE)[(2*(c) + 1)*8 + q]; \
    const ulonglong2 wC = (WO)[(2*(c)    )*8 + q]; \
    const ulonglong2 wD = (WO)[(2*(c) + 1)*8 + q]; \
    FMA2(f0, hv.x, wA.x, f0); FMA2(f1, hv.x, wA.y, f1); \
    FMA2(f2, hv.x, wC.x, f2); FMA2(f3, hv.x, wC.y, f3); \
    FMA2(f0, hv.y, wB.x, f0); FMA2(f1, hv.y, wB.y, f1); \
    FMA2(f2, hv.y, wD.x, f2); FMA2(f3, hv.y, wD.y, f3); \
    const ulonglong2 u0 = ((const ulonglong2*)((TB)      ))[c]; \
    const ulonglong2 u1 = ((const ulonglong2*)((TB) + 32 ))[c]; \
    const ulonglong2 u2 = ((const ulonglong2*)((TB) + 64 ))[c]; \
    FMA2(t00,u0.x,wA.x,t00); FMA2(t01,u0.x,wA.y,t01); FMA2(t02,u0.x,wC.x,t02); FMA2(t03,u0.x,wC.y,t03); \
    FMA2(t00,u0.y,wB.x,t00); FMA2(t01,u0.y,wB.y,t01); FMA2(t02,u0.y,wD.x,t02); FMA2(t03,u0.y,wD.y,t03); \
    FMA2(t10,u1.x,wA.x,t10); FMA2(t11,u1.x,wA.y,t11); FMA2(t12,u1.x,wC.x,t12); FMA2(t13,u1.x,wC.y,t13); \
    FMA2(t10,u1.y,wB.x,t10); FMA2(t11,u1.y,wB.y,t11); FMA2(t12,u1.y,wD.x,t12); FMA2(t13,u1.y,wD.y,t13); \
    FMA2(t20,u2.x,wA.x,t20); FMA2(t21,u2.x,wA.y,t21); FMA2(t22,u2.x,wC.x,t22); FMA2(t23,u2.x,wC.y,t23); \
    FMA2(t20,u2.y,wB.x,t20); FMA2(t21,u2.y,wB.y,t21); FMA2(t22,u2.y,wD.x,t22); FMA2(t23,u2.y,wD.y,t23); }

#define LAYER(WE, WO, HB, TB) \
    CHUNK(WE,WO,HB,TB,0) CHUNK(WE,WO,HB,TB,1) CHUNK(WE,WO,HB,TB,2) CHUNK(WE,WO,HB,TB,3) \
    CHUNK(WE,WO,HB,TB,4) CHUNK(WE,WO,HB,TB,5) CHUNK(WE,WO,HB,TB,6) CHUNK(WE,WO,HB,TB,7)

// exchange buffer: per warp 4 samples x 260 floats (1040B stride = 16 mod 128
// -> the 4 samples' chunk lines land in distinct banks: 1 wavefront/LDS.128)
#define SMP_F 260
#define WARP_F (4 * SMP_F)

__global__ __launch_bounds__(BLOCK, 4) void NCL_50766513438744_kernel(
    const float* __restrict__ x,
    const float* __restrict__ W1, const float* __restrict__ b1,
    const float* __restrict__ W2, const float* __restrict__ b2,
    const float* __restrict__ W3, const float* __restrict__ b3,
    const float* __restrict__ W4,
    float* __restrict__ out, int N, int totalWarps)
{
    // blocked weights: E[i*8+q] = 2x2 block (kpair i, cols 4q,4q+1),
    //                  O[i*8+q] = (kpair i, cols 4q+2,4q+3)
    __shared__ __align__(16) ulonglong2 sW2E[128], sW2O[128], sW3E[128], sW3O[128];
    __shared__ __align__(16) float sBuf[WPB * WARP_F];

    {
        const int t = threadIdx.x;           // 128 threads -> one entry each
        const int i = t >> 3, qq = t & 7;
        const int c0 = 4 * qq;
        float4 v;
        v = make_float4(W2[(2*i)*32 + c0],     W2[(2*i+1)*32 + c0],
                        W2[(2*i)*32 + c0 + 1], W2[(2*i+1)*32 + c0 + 1]);
        ((float4*)sW2E)[t] = v;
        v = make_float4(W2[(2*i)*32 + c0 + 2], W2[(2*i+1)*32 + c0 + 2],
                        W2[(2*i)*32 + c0 + 3], W2[(2*i+1)*32 + c0 + 3]);
        ((float4*)sW2O)[t] = v;
        v = make_float4(W3[(2*i)*32 + c0],     W3[(2*i+1)*32 + c0],
                        W3[(2*i)*32 + c0 + 1], W3[(2*i+1)*32 + c0 + 1]);
        ((float4*)sW3E)[t] = v;
        v = make_float4(W3[(2*i)*32 + c0 + 2], W3[(2*i+1)*32 + c0 + 2],
                        W3[(2*i)*32 + c0 + 3], W3[(2*i+1)*32 + c0 + 3]);
        ((float4*)sW3O)[t] = v;
    }
    __syncthreads();

    const int lane = threadIdx.x & 31;
    const int wib  = threadIdx.x >> 5;
    const int smp  = lane >> 3;          // sample slot 0..3
    const int q    = lane & 7;           // column quad: cols 4q..4q+3
    const int cb   = 4 * q;

    float* const sb  = &sBuf[wib * WARP_F + smp * SMP_F];
    float* const hb1 = sb;               // h1 [32]
    float* const hb2 = sb + 32;          // h2 [32]
    float* const tb1 = sb + 64;          // t1 [3][32]
    float* const tb2 = sb + 160;         // t2 [3][32]

    // per-lane constants for this lane's 4 columns
    const float w1a0 = W1[cb+0], w1a1 = W1[cb+1], w1a2 = W1[cb+2], w1a3 = W1[cb+3];
    const float w1b0 = W1[32+cb+0], w1b1 = W1[32+cb+1], w1b2 = W1[32+cb+2], w1b3 = W1[32+cb+3];
    const float w1c0 = W1[64+cb+0], w1c1 = W1[64+cb+1], w1c2 = W1[64+cb+2], w1c3 = W1[64+cb+3];
    const float b1r0 = b1[cb+0], b1r1 = b1[cb+1], b1r2 = b1[cb+2], b1r3 = b1[cb+3];
    const float b2r0 = b2[cb+0], b2r1 = b2[cb+1], b2r2 = b2[cb+2], b2r3 = b2[cb+3];
    const float b3r0 = b3[cb+0], b3r1 = b3[cb+1], b3r2 = b3[cb+2], b3r3 = b3[cb+3];
    const float w4_00 = W4[(cb+0)*3+0], w4_01 = W4[(cb+0)*3+1], w4_02 = W4[(cb+0)*3+2];
    const float w4_10 = W4[(cb+1)*3+0], w4_11 = W4[(cb+1)*3+1], w4_12 = W4[(cb+1)*3+2];
    const float w4_20 = W4[(cb+2)*3+0], w4_21 = W4[(cb+2)*3+1], w4_22 = W4[(cb+2)*3+2];
    const float w4_30 = W4[(cb+3)*3+0], w4_31 = W4[(cb+3)*3+1], w4_32 = W4[(cb+3)*3+2];

    const int nGroups = (N + 3) >> 2;
    const int gw = blockIdx.x * WPB + wib;
    if (gw >= nGroups) return;

    int myIdx = 4 * gw + smp; if (myIdx >= N) myIdx = N - 1;
    float x0 = __ldg(x + 3 * myIdx + 0);
    float x1 = __ldg(x + 3 * myIdx + 1);
    float x2 = __ldg(x + 3 * myIdx + 2);

    for (int g = gw; g < nGroups; g += totalWarps) {
        const int sIdx = 4 * g + smp;

        // ===== phase A: layer 1 + tangent seeds for 4 columns =====
        float h0, h1v, h2v, h3v, d0, d1v, d2v, d3v;
        act_hd(fmaf(x0, w1a0, fmaf(x1, w1b0, fmaf(x2, w1c0, b1r0))), h0,  d0);
        act_hd(fmaf(x0, w1a1, fmaf(x1, w1b1, fmaf(x2, w1c1, b1r1))), h1v, d1v);
        act_hd(fmaf(x0, w1a2, fmaf(x1, w1b2, fmaf(x2, w1c2, b1r2))), h2v, d2v);
        act_hd(fmaf(x0, w1a3, fmaf(x1, w1b3, fmaf(x2, w1c3, b1r3))), h3v, d3v);
        ((float4*)hb1)[q] = make_float4(h0, h1v, h2v, h3v);
        ((float4*)(tb1     ))[q] = make_float4(d0*w1a0, d1v*w1a1, d2v*w1a2, d3v*w1a3);
        ((float4*)(tb1 + 32))[q] = make_float4(d0*w1b0, d1v*w1b1, d2v*w1b2, d3v*w1b3);
        ((float4*)(tb1 + 64))[q] = make_float4(d0*w1c0, d1v*w1c1, d2v*w1c2, d3v*w1c3);
        __syncwarp();

        // prefetch next group's x
        {
            const int gn = g + totalWarps;
            int nIdx = 4 * gn + smp;
            if (nIdx >= N) nIdx = N - 1;
            x0 = __ldg(x + 3 * nIdx + 0);
            x1 = __ldg(x + 3 * nIdx + 1);
            x2 = __ldg(x + 3 * nIdx + 2);
        }

        // ===== phase B: layer-2 forward + tangent layer 2 =====
        ull f0 = pk2(b2r0, 0.f), f1 = pk2(b2r1, 0.f), f2 = pk2(b2r2, 0.f), f3 = pk2(b2r3, 0.f);
        ull t00=0ull,t01=0ull,t02=0ull,t03=0ull,
            t10=0ull,t11=0ull,t12=0ull,t13=0ull,
            t20=0ull,t21=0ull,t22=0ull,t23=0ull;
        LAYER(sW2E, sW2O, hb1, tb1)
        act_hd(hadd2(f0), h0,  d0);
        act_hd(hadd2(f1), h1v, d1v);
        act_hd(hadd2(f2), h2v, d2v);
        act_hd(hadd2(f3), h3v, d3v);
        ((float4*)hb2)[q] = make_float4(h0, h1v, h2v, h3v);
        ((float4*)(tb2     ))[q] = make_float4(d0*hadd2(t00), d1v*hadd2(t01), d2v*hadd2(t02), d3v*hadd2(t03));
        ((float4*)(tb2 + 32))[q] = make_float4(d0*hadd2(t10), d1v*hadd2(t11), d2v*hadd2(t12), d3v*hadd2(t13));
        ((float4*)(tb2 + 64))[q] = make_float4(d0*hadd2(t20), d1v*hadd2(t21), d2v*hadd2(t22), d3v*hadd2(t23));
        __syncwarp();

        // ===== phase C: layer-3 forward (deriv only) + tangent layer 3 =====
        f0 = pk2(b3r0, 0.f); f1 = pk2(b3r1, 0.f); f2 = pk2(b3r2, 0.f); f3 = pk2(b3r3, 0.f);
        t00=0ull;t01=0ull;t02=0ull;t03=0ull;
        t10=0ull;t11=0ull;t12=0ull;t13=0ull;
        t20=0ull;t21=0ull;t22=0ull;t23=0ull;
        LAYER(sW3E, sW3O, hb2, tb2)
        d0  = act_d(hadd2(f0));
        d1v = act_d(hadd2(f1));
        d2v = act_d(hadd2(f2));
        d3v = act_d(hadd2(f3));
        const float s00 = d0*hadd2(t00), s01 = d1v*hadd2(t01), s02 = d2v*hadd2(t02), s03 = d3v*hadd2(t03);
        const float s10 = d0*hadd2(t10), s11 = d1v*hadd2(t11), s12 = d2v*hadd2(t12), s13 = d3v*hadd2(t13);
        const float s20 = d0*hadd2(t20), s21 = d1v*hadd2(t21), s22 = d2v*hadd2(t22), s23 = d3v*hadd2(t23);

        // layer 4 + antisymmetric trace contraction over this lane's 4 cols
        float po0 = fmaf(s10, w4_00, s20 * w4_01)
                  + fmaf(s11, w4_10, s21 * w4_11)
                  + fmaf(s12, w4_20, s22 * w4_21)
                  + fmaf(s13, w4_30, s23 * w4_31);
        float po1 = fmaf(s20, w4_02, -(s00 * w4_00))
                  + fmaf(s21, w4_12, -(s01 * w4_10))
                  + fmaf(s22, w4_22, -(s02 * w4_20))
                  + fmaf(s23, w4_32, -(s03 * w4_30));
        float po2 = -(fmaf(s00, w4_01, s10 * w4_02)
                    + fmaf(s01, w4_11, s11 * w4_12)
                    + fmaf(s02, w4_21, s12 * w4_22)
                    + fmaf(s03, w4_31, s13 * w4_32));

        // reduce over the 8 lanes of this quarter
        #pragma unroll
        for (int off = 4; off; off >>= 1) {
            po0 += __shfl_xor_sync(0xffffffffu, po0, off);
            po1 += __shfl_xor_sync(0xffffffffu, po1, off);
            po2 += __shfl_xor_sync(0xffffffffu, po2, off);
        }
        if (q == 0 && sIdx < N) {
            out[3 * sIdx + 0] = po0;
            out[3 * sIdx + 1] = po1;
            out[3 * sIdx + 2] = po2;
        }
        // loop-carried buffer hazards covered by the two syncwarps per iter
    }
}

extern "C" void kernel_launch(void* const* d_in, const int* in_sizes, int n_in,
                              void* d_out, int out_size) {
    const float* x  = (const float*)d_in[0];
    const float* W1 = (const float*)d_in[1];
    const float* b1 = (const float*)d_in[2];
    const float* W2 = (const float*)d_in[3];
    const float* b2 = (const float*)d_in[4];
    const float* W3 = (const float*)d_in[5];
    const float* b3 = (const float*)d_in[6];
    const float* W4 = (const float*)d_in[7];
    // d_in[8] = b4: not needed (bias drops out of the Jacobian)
    float* out = (float*)d_out;

    const int N = in_sizes[0] / 3;
    const int totalWarps = GRID * WPB;
    NCL_50766513438744_kernel<<<GRID, BLOCK>>>(x, W1, b1, W2, b2, W3, b3, W4,
                                               out, N, totalWarps);
}